// round 15
// baseline (speedup 1.0000x reference)
#include <cuda_runtime.h>

#define BB 64
#define SS 512
#define HH 768
#define LL 9
#define BS (BB*SS)
#define FULLM 0xffffffffu

__device__ float    g_logits[BS*LL + 256];   // pad: harmless reads for t>=512 prefetch
__device__ float    g_nd[BB];
__device__ unsigned g_ctr;

__device__ __forceinline__ float ex2f(float x){ float y; asm("ex2.approx.ftz.f32 %0,%1;" : "=f"(y) : "f"(x)); return y; }
__device__ __forceinline__ float lg2f(float x){ float y; asm("lg2.approx.ftz.f32 %0,%1;" : "=f"(y) : "f"(x)); return y; }
__device__ __forceinline__ float max9(const float* v){
    float m01 = fmaxf(v[0], v[1]), m23 = fmaxf(v[2], v[3]);
    float m45 = fmaxf(v[4], v[5]), m67 = fmaxf(v[6], v[7]);
    return fmaxf(fmaxf(fmaxf(m01, m23), fmaxf(m45, m67)), v[8]);
}

// ================= 1. GEMM (R12 proven, unchanged) =================
__global__ void __launch_bounds__(256) gemm_kernel(const float* __restrict__ hidden,
                                                   const float* __restrict__ W,
                                                   const float* __restrict__ bvec) {
    __shared__ float w_t[LL*HH];
    __shared__ float b_s[LL];
    int tid = threadIdx.x;
    for (int i = tid; i < HH*LL; i += 256) {
        int k = i / LL, l = i - k*LL;
        w_t[l*HH + k] = W[i];
    }
    if (tid < LL) b_s[tid] = bvec[tid];
    __syncthreads();

    int warp = tid >> 5, ln = tid & 31;
    int li = ln & 7, rg = ln >> 3;
    int row0 = blockIdx.x * 64 + warp * 8 + rg * 2;
    const float* hp = hidden + (size_t)row0 * HH;

    float acc0[LL], acc1[LL];
    #pragma unroll
    for (int l = 0; l < LL; l++) { acc0[l] = 0.f; acc1[l] = 0.f; }

    #pragma unroll 4
    for (int c = 0; c < HH/32; c++) {
        int kb = c*32 + li*4;
        float4 x0 = *reinterpret_cast<const float4*>(hp + kb);
        float4 x1 = *reinterpret_cast<const float4*>(hp + HH + kb);
        #pragma unroll
        for (int l = 0; l < LL; l++) {
            float4 w4 = *reinterpret_cast<const float4*>(w_t + l*HH + kb);
            acc0[l] += x0.x*w4.x; acc1[l] += x1.x*w4.x;
            acc0[l] += x0.y*w4.y; acc1[l] += x1.y*w4.y;
            acc0[l] += x0.z*w4.z; acc1[l] += x1.z*w4.z;
            acc0[l] += x0.w*w4.w; acc1[l] += x1.w*w4.w;
        }
    }
    #pragma unroll
    for (int l = 0; l < LL; l++) {
        float v0 = acc0[l], v1 = acc1[l];
        v0 += __shfl_xor_sync(FULLM, v0, 4); v1 += __shfl_xor_sync(FULLM, v1, 4);
        v0 += __shfl_xor_sync(FULLM, v0, 2); v1 += __shfl_xor_sync(FULLM, v1, 2);
        v0 += __shfl_xor_sync(FULLM, v0, 1); v1 += __shfl_xor_sync(FULLM, v1, 1);
        acc0[l] = v0; acc1[l] = v1;
    }
    if (li == 0) {
        float* op0 = g_logits + (size_t)row0 * LL;
        float* op1 = op0 + LL;
        #pragma unroll
        for (int l = 0; l < LL; l++) { op0[l] = acc0[l] + b_s[l]; op1[l] = acc1[l] + b_s[l]; }
    }
}

// shared raw layout (bytes)
#define SH_S     0        // vit: s_sh 513*9 floats = 18468 | lognorm: em_s
#define SH_M     18480    // SS+1 bytes
#define SH_TR    19008    // vit: 81 floats
#define SH_SEG   19392    // vit: 72*64 = 4608 -> 24000
#define SH_LNM   19392    // lognorm: 2*81 floats
#define SH_TOTAL 24064

// ================= 2. fused CRF =================
// vit blocks: warp 7 runs the EXACT chain in 5-shfl/step form (27 lanes, 3-state
// locals; fp-max regrouping is exact); scores stored, backpointers recomputed in
// the parallel backtrack. lognorm blocks unchanged (R12/R14 proven).
__global__ void __launch_bounds__(256) fused_kernel(const int* __restrict__ mask,
                                                    const int* __restrict__ labels,
                                                    const float* __restrict__ st,
                                                    const float* __restrict__ en,
                                                    const float* __restrict__ tr,
                                                    float* __restrict__ out) {
    const float L2E = 1.4426950408889634f;
    __shared__ __align__(16) unsigned char shraw[SH_TOTAL];
    __shared__ int best_last_sh;
    __shared__ unsigned char chosen[8];
    __shared__ int last_sh;

    int bid = blockIdx.x;
    int tid = threadIdx.x;
    int w = tid >> 5, lane = tid & 31;
    int isVit = (bid < BB);
    int b = isVit ? bid : (bid - BB);

    unsigned char* m_sh = shraw + SH_M;
    const int* mp = mask + b * SS;

    if (isVit) {
        float* s_sh  = (float*)(shraw + SH_S);     // [513][9]
        float* tr_sh = (float*)(shraw + SH_TR);    // [81]
        unsigned char (*seg)[64] = (unsigned char (*)[64])(shraw + SH_SEG);

        if (w < 7) {
            // ---- stage mask + transitions while warp 7 runs the chain ----
            for (int k = tid; k < SS; k += 224) m_sh[k] = (unsigned char)(mp[k] != 0);
            if (tid < 81) tr_sh[tid] = tr[tid];
            if (tid == 0) m_sh[SS] = 0;
        } else {
            // -------- EXACT sequential Viterbi, 5 shfls/step --------
            int g = lane / 9, j = lane - g*9;
            if (g > 2) { g = 0; j = lane - 27; }       // lanes 27..31 shadow
            int base3 = 3*g;
            int srcA = ((g+1)%3)*9 + j;
            int srcB = ((g+2)%3)*9 + j;
            const float* gl = g_logits + (size_t)b * SS * LL;

            float Trow0 = tr[(base3+0)*LL + j];
            float Trow1 = tr[(base3+1)*LL + j];
            float Trow2 = tr[(base3+2)*LL + j];
            float diag0 = (base3+0 == j) ? 0.f : -1e30f;
            float diag1 = (base3+1 == j) ? 0.f : -1e30f;
            float diag2 = (base3+2 == j) ? 0.f : -1e30f;

            float s_loc0 = st[base3+0] + gl[base3+0];
            float s_loc1 = st[base3+1] + gl[base3+1];
            float s_loc2 = st[base3+2] + gl[base3+2];
            float own    = st[j] + gl[j];
            if (lane < 9) s_sh[j] = own;               // t = 0

            float emA[8], emB[8];
            int   mA[8],  mB[8];
            #pragma unroll
            for (int k = 0; k < 8; k++) {
                emA[k] = gl[(k+1)*LL + j];
                mA[k]  = mp[k+1];
            }

            for (int tt = 0; tt < 64; tt++) {
                int tb = tt*8 + 9;
                #pragma unroll
                for (int k = 0; k < 8; k++) {
                    emB[k] = gl[(tb + k)*LL + j];       // pad covers t>511
                    mB[k]  = (tb + k <= SS-1) ? mp[tb + k] : 0;
                }
                #pragma unroll
                for (int k = 0; k < 8; k++) {
                    int t = tt*8 + k + 1;               // 1..512 (512 = masked pad)
                    int m_c = mA[k];
                    float tw0 = m_c ? Trow0 : diag0;    // off-chain
                    float tw1 = m_c ? Trow1 : diag1;
                    float tw2 = m_c ? Trow2 : diag2;
                    float eme = m_c ? emA[k] : 0.f;
                    float c0 = s_loc0 + tw0;
                    float c1 = s_loc1 + tw1;
                    float c2 = s_loc2 + tw2;
                    float part = fmaxf(fmaxf(c0, c1), c2);
                    float pA = __shfl_sync(FULLM, part, srcA);
                    float pB = __shfl_sync(FULLM, part, srcB);
                    own = fmaxf(fmaxf(part, pA), pB) + eme;   // exact: max is order-invariant
                    if (lane < 9) s_sh[t*LL + j] = own;
                    s_loc0 = __shfl_sync(FULLM, own, base3 + 0);
                    s_loc1 = __shfl_sync(FULLM, own, base3 + 1);
                    s_loc2 = __shfl_sync(FULLM, own, base3 + 2);
                }
                #pragma unroll
                for (int k = 0; k < 8; k++) { emA[k] = emB[k]; mA[k] = mB[k]; }
            }
            float fin = (lane < 9) ? (own + en[j]) : -1e30f;
            float bv = -1e30f; int bl = 0;
            #pragma unroll
            for (int i = 0; i < LL; i++) {
                float f = __shfl_sync(FULLM, fin, i);
                if (f > bv) { bv = f; bl = i; }         // first-max wins
            }
            if (lane == 0) best_last_sh = bl;
        }
        __syncthreads();

        // ---- 72 parallel chases; argmax RECOMPUTED from stored scores (bit-identical) ----
        if (tid < 72) {
            int c = tid / 9, e = tid - c*9;
            int thi = (c == 7) ? (SS-1) : (c*64 + 64);
            int cur = e;
            for (int t = thi; t >= c*64 + 1; t--) {
                const float* sp = s_sh + (t-1)*LL;
                float v[LL];
                #pragma unroll
                for (int i = 0; i < LL; i++) v[i] = sp[i] + tr_sh[i*LL + cur];
                float best = max9(v);
                int bi = 8;
                #pragma unroll
                for (int i = 7; i >= 0; i--) bi = (v[i] == best) ? i : bi;   // first-max wins
                cur = m_sh[t] ? bi : cur;
                seg[c*9 + e][t - 1 - c*64] = (unsigned char)cur;
            }
        }
        __syncthreads();
        if (tid == 0) {
            int cur = best_last_sh;
            chosen[7] = (unsigned char)cur;
            for (int c = 7; c >= 1; c--) {
                cur = seg[c*9 + cur][0];
                chosen[c-1] = (unsigned char)cur;
            }
        }
        __syncthreads();

        // ---- one-hot ----
        float* outp = out + 1 + (size_t)b * SS * LL;
        int bl = best_last_sh;
        for (int idx = tid; idx < SS*LL; idx += 256) {
            int t = idx / LL;
            int l = idx - t*LL;
            int c = t >> 6;
            int tag = (t == SS-1) ? bl : (int)seg[c*9 + chosen[c]][t & 63];
            outp[idx] = (m_sh[t] && tag == l) ? 1.f : 0.f;
        }
    } else {
        // ---------------- lognorm blocks (R12 proven, unchanged) ----------------
        float* em_s = (float*)(shraw + SH_S);
        {
            const float4* src = reinterpret_cast<const float4*>(g_logits + (size_t)b * SS * LL);
            float4* dst = reinterpret_cast<float4*>(em_s);
            for (int k = tid; k < SS*LL/4; k += 256) dst[k] = src[k];
            for (int k = tid; k < SS; k += 256) m_sh[k] = (unsigned char)(mp[k] != 0);
            if (tid < LL) em_s[SS*LL + tid] = 0.f;
            if (tid == 0) m_sh[SS] = 0;
        }
        __syncthreads();

        float* lnM_s = (float*)(shraw + SH_LNM);
        if (w < 6) {
            int c = w / 3, trio = w - c*3;
            int gg = lane / 9, jj = lane - gg*9;
            if (gg > 2) { gg = 0; jj = lane - 27; }
            int gbase = gg * 9;
            bool act = (lane < 27);
            int e = trio*3 + gg;

            float u[LL];
            #pragma unroll
            for (int k = 0; k < LL; k++) u[k] = ex2f(tr[k*LL + jj] * L2E);

            float wv = (act && jj == e) ? 1.f : 0.f;
            int Ce = 0;
            int t0 = c*256 + 1;
            for (int oo = 0; oo < 32; oo++) {
                #pragma unroll
                for (int k = 0; k < 8; k++) {
                    int t = t0 + oo*8 + k;
                    float pe = ex2f(em_s[t*LL + jj] * L2E);
                    int m = m_sh[t];
                    float wi[LL];
                    #pragma unroll
                    for (int q = 0; q < LL; q++) wi[q] = __shfl_sync(FULLM, wv, gbase + q) * u[q];
                    float p = ((wi[0]+wi[1]) + (wi[2]+wi[3])) + ((wi[4]+wi[5]) + (wi[6]+wi[7])) + wi[8];
                    float nw = p * pe;
                    wv = m ? nw : wv;
                }
                float mx = wv;
                #pragma unroll
                for (int q = 0; q < LL; q++) mx = fmaxf(mx, __shfl_sync(FULLM, wv, gbase + q));
                int e2 = ((__float_as_int(mx) >> 23) & 0xFF) - 127;
                Ce += e2;
                wv *= __int_as_float((127 - e2) << 23);
            }
            if (act) lnM_s[(c*LL + e)*LL + jj] = lg2f(wv) + (float)Ce;
            asm volatile("bar.sync 1, 224;" ::: "memory");
        } else if (w == 6) {
            const int* lp = labels + b * SS;
            float acc = 0.f; int cnt = 0;
            for (int t = lane; t < SS; t += 32) {
                int m = m_sh[t]; cnt += m;
                if (t >= 1 && m) {
                    int tg = lp[t];   if (tg == -100) tg = 0;
                    int tp = lp[t-1]; if (tp == -100) tp = 0;
                    acc += em_s[t*LL + tg] + tr[tp*LL + tg];
                }
            }
            #pragma unroll
            for (int o = 16; o > 0; o >>= 1) {
                acc += __shfl_down_sync(FULLM, acc, o);
                cnt += __shfl_down_sync(FULLM, cnt, o);
            }
            float num = 0.f;
            if (lane == 0) {
                int t0 = lp[0]; if (t0 == -100) t0 = 0;
                int lt = lp[cnt - 1]; if (lt == -100) lt = 0;
                num = st[t0] + em_s[t0] + acc + en[lt];
            }
            asm volatile("bar.sync 1, 224;" ::: "memory");

            int j2 = (lane < LL) ? lane : (LL-1);
            bool l9 = (lane < LL);
            float v = l9 ? (st[j2] + em_s[j2]) * L2E : -1e30f;
            #pragma unroll
            for (int c = 0; c < 2; c++) {
                float s[LL];
                #pragma unroll
                for (int i = 0; i < LL; i++) s[i] = __shfl_sync(FULLM, v, i) + lnM_s[(c*LL + i)*LL + j2];
                float mx = max9(s);
                float p = 0.f;
                #pragma unroll
                for (int i = 0; i < LL; i++) p += ex2f(s[i] - mx);
                v = mx + lg2f(p);
            }
            float F = l9 ? (v + en[j2] * L2E) : -1e30f;
            float fv[LL];
            #pragma unroll
            for (int i = 0; i < LL; i++) fv[i] = __shfl_sync(FULLM, F, i);
            float mx = max9(fv);
            float p = 0.f;
            #pragma unroll
            for (int i = 0; i < LL; i++) p += ex2f(fv[i] - mx);
            if (lane == 0) {
                g_nd[b] = num - (mx + lg2f(p)) * (1.0f / L2E);
                __threadfence();
            }
        }
    }

    // ================= last block: loss + counter reset =================
    __syncthreads();
    if (tid == 0) {
        __threadfence();
        unsigned o = atomicAdd(&g_ctr, 1u);
        last_sh = (o == 2*BB - 1);
    }
    __syncthreads();
    if (last_sh) {
        __threadfence();
        if (tid < 32) {
            float x = g_nd[tid] + g_nd[tid + 32];
            #pragma unroll
            for (int o = 16; o > 0; o >>= 1) x += __shfl_down_sync(FULLM, x, o);
            if (tid == 0) { out[0] = -x / (float)BB; g_ctr = 0; }
        }
    }
}

extern "C" void kernel_launch(void* const* d_in, const int* in_sizes, int n_in,
                              void* d_out, int out_size) {
    const float* hidden = (const float*)d_in[0];
    const int*   mask   = (const int*)  d_in[1];
    const int*   labels = (const int*)  d_in[2];
    const float* W      = (const float*)d_in[3];
    const float* bvec   = (const float*)d_in[4];
    const float* st     = (const float*)d_in[5];
    const float* en     = (const float*)d_in[6];
    const float* tr     = (const float*)d_in[7];
    float* out = (float*)d_out;

    gemm_kernel<<<BS/64, 256>>>(hidden, W, bvec);
    fused_kernel<<<2*BB, 256>>>(mask, labels, st, en, tr, out);
}

// round 16
// speedup vs baseline: 1.1594x; 1.1594x over previous
#include <cuda_runtime.h>

#define BB 64
#define SS 512
#define HH 768
#define LL 9
#define BS (BB*SS)
#define FULLM 0xffffffffu

__device__ float    g_logits[BS*LL + 256];   // pad: harmless reads for t>=512 prefetch
__device__ float    g_nd[BB];
__device__ unsigned g_ctr;

__device__ __forceinline__ float ex2f(float x){ float y; asm("ex2.approx.ftz.f32 %0,%1;" : "=f"(y) : "f"(x)); return y; }
__device__ __forceinline__ float lg2f(float x){ float y; asm("lg2.approx.ftz.f32 %0,%1;" : "=f"(y) : "f"(x)); return y; }
__device__ __forceinline__ float max9(const float* v){
    float m01 = fmaxf(v[0], v[1]), m23 = fmaxf(v[2], v[3]);
    float m45 = fmaxf(v[4], v[5]), m67 = fmaxf(v[6], v[7]);
    return fmaxf(fmaxf(fmaxf(m01, m23), fmaxf(m45, m67)), v[8]);
}

// ================= 1. GEMM (R12 proven, unchanged) =================
__global__ void __launch_bounds__(256) gemm_kernel(const float* __restrict__ hidden,
                                                   const float* __restrict__ W,
                                                   const float* __restrict__ bvec) {
    __shared__ float w_t[LL*HH];
    __shared__ float b_s[LL];
    int tid = threadIdx.x;
    for (int i = tid; i < HH*LL; i += 256) {
        int k = i / LL, l = i - k*LL;
        w_t[l*HH + k] = W[i];
    }
    if (tid < LL) b_s[tid] = bvec[tid];
    __syncthreads();

    int warp = tid >> 5, ln = tid & 31;
    int li = ln & 7, rg = ln >> 3;
    int row0 = blockIdx.x * 64 + warp * 8 + rg * 2;
    const float* hp = hidden + (size_t)row0 * HH;

    float acc0[LL], acc1[LL];
    #pragma unroll
    for (int l = 0; l < LL; l++) { acc0[l] = 0.f; acc1[l] = 0.f; }

    #pragma unroll 4
    for (int c = 0; c < HH/32; c++) {
        int kb = c*32 + li*4;
        float4 x0 = *reinterpret_cast<const float4*>(hp + kb);
        float4 x1 = *reinterpret_cast<const float4*>(hp + HH + kb);
        #pragma unroll
        for (int l = 0; l < LL; l++) {
            float4 w4 = *reinterpret_cast<const float4*>(w_t + l*HH + kb);
            acc0[l] += x0.x*w4.x; acc1[l] += x1.x*w4.x;
            acc0[l] += x0.y*w4.y; acc1[l] += x1.y*w4.y;
            acc0[l] += x0.z*w4.z; acc1[l] += x1.z*w4.z;
            acc0[l] += x0.w*w4.w; acc1[l] += x1.w*w4.w;
        }
    }
    #pragma unroll
    for (int l = 0; l < LL; l++) {
        float v0 = acc0[l], v1 = acc1[l];
        v0 += __shfl_xor_sync(FULLM, v0, 4); v1 += __shfl_xor_sync(FULLM, v1, 4);
        v0 += __shfl_xor_sync(FULLM, v0, 2); v1 += __shfl_xor_sync(FULLM, v1, 2);
        v0 += __shfl_xor_sync(FULLM, v0, 1); v1 += __shfl_xor_sync(FULLM, v1, 1);
        acc0[l] = v0; acc1[l] = v1;
    }
    if (li == 0) {
        float* op0 = g_logits + (size_t)row0 * LL;
        float* op1 = op0 + LL;
        #pragma unroll
        for (int l = 0; l < LL; l++) { op0[l] = acc0[l] + b_s[l]; op1[l] = acc1[l] + b_s[l]; }
    }
}

// shared raw layout (bytes)
#define SROW 12                        // padded score-row stride (floats)
#define SH_S     0                     // vit: s_sh [513][12] = 24624 | lognorm: em_s (18504)
#define SH_M     24624                 // SS+1 bytes -> 25137
#define SH_TR    25144                 // vit: 81 floats -> 25468
#define SH_SEG   25472                 // vit: 72*64 -> 30080
#define SH_LNM   25144                 // lognorm: 2*81 floats (overlaps TR; disjoint block roles)
#define SH_TOTAL 30080

// ================= 2. fused CRF =================
// vit blocks: warp 7 runs the EXACT chain with smem-broadcast exchange (3x LDS.128
// + STS + syncwarp, NO per-step shfl). Scores stored; backpointers recomputed in
// the parallel backtrack (R14-proven). Lognorm blocks unchanged (R12-proven).
__global__ void __launch_bounds__(256) fused_kernel(const int* __restrict__ mask,
                                                    const int* __restrict__ labels,
                                                    const float* __restrict__ st,
                                                    const float* __restrict__ en,
                                                    const float* __restrict__ tr,
                                                    float* __restrict__ out) {
    const float L2E = 1.4426950408889634f;
    __shared__ __align__(16) unsigned char shraw[SH_TOTAL];
    __shared__ int best_last_sh;
    __shared__ unsigned char chosen[8];
    __shared__ int last_sh;

    int bid = blockIdx.x;
    int tid = threadIdx.x;
    int w = tid >> 5, lane = tid & 31;
    int isVit = (bid < BB);
    int b = isVit ? bid : (bid - BB);

    unsigned char* m_sh = shraw + SH_M;
    const int* mp = mask + b * SS;

    if (isVit) {
        float* s_sh  = (float*)(shraw + SH_S);     // [513][SROW]
        float* tr_sh = (float*)(shraw + SH_TR);    // [81]
        unsigned char (*seg)[64] = (unsigned char (*)[64])(shraw + SH_SEG);

        if (w < 7) {
            // ---- stage mask + transitions while warp 7 runs the chain ----
            for (int k = tid; k < SS; k += 224) m_sh[k] = (unsigned char)(mp[k] != 0);
            if (tid < 81) tr_sh[tid] = tr[tid];
            if (tid == 0) m_sh[SS] = 0;
        } else {
            // -------- EXACT sequential Viterbi, smem-broadcast exchange --------
            bool lane9 = (lane < LL);
            int j = lane;
            const float* gl = g_logits + (size_t)b * SS * LL;
            float trow[LL], diag[LL];
            #pragma unroll
            for (int i = 0; i < LL; i++) {
                trow[i] = lane9 ? tr[i*LL + j] : 0.f;
                diag[i] = (i == j) ? 0.f : -1e30f;
            }
            float own = lane9 ? (st[j] + gl[j]) : 0.f;
            if (lane9) s_sh[j] = own;                   // row 0
            __syncwarp();

            float emA[16], emB[16];
            int   mA[16],  mB[16];
            #pragma unroll
            for (int k = 0; k < 16; k++) {
                emA[k] = lane9 ? gl[(k+1)*LL + j] : 0.f;
                mA[k]  = mp[k+1];
            }

            for (int tt = 0; tt < 32; tt++) {
                int tb = tt*16 + 17;
                #pragma unroll
                for (int k = 0; k < 16; k++) {
                    emB[k] = lane9 ? gl[(tb + k)*LL + j] : 0.f;   // pad covers tail
                    mB[k]  = (tb + k <= SS-1) ? mp[tb + k] : 0;
                }
                #pragma unroll
                for (int k = 0; k < 16; k++) {
                    int t = tt*16 + k + 1;              // 1..512 (512 = masked no-op)
                    int m_c = mA[k];
                    // masked-step algebra: tw=diag, em'=0 -> own_j = s_j exactly
                    float tw[LL];
                    #pragma unroll
                    for (int i = 0; i < LL; i++) tw[i] = m_c ? trow[i] : diag[i];
                    float eme = m_c ? emA[k] : 0.f;

                    const float* srow = s_sh + (size_t)(t-1)*SROW;
                    float4 sA = *reinterpret_cast<const float4*>(srow);
                    float4 sB = *reinterpret_cast<const float4*>(srow + 4);
                    float4 sC = *reinterpret_cast<const float4*>(srow + 8);
                    float v[LL];
                    v[0] = sA.x + tw[0]; v[1] = sA.y + tw[1]; v[2] = sA.z + tw[2];
                    v[3] = sA.w + tw[3]; v[4] = sB.x + tw[4]; v[5] = sB.y + tw[5];
                    v[6] = sB.z + tw[6]; v[7] = sB.w + tw[7]; v[8] = sC.x + tw[8];
                    own = max9(v) + eme;
                    if (lane9) s_sh[(size_t)t*SROW + j] = own;
                    __syncwarp();
                }
                #pragma unroll
                for (int k = 0; k < 16; k++) { emA[k] = emB[k]; mA[k] = mB[k]; }
            }
            float fin = lane9 ? (own + en[j]) : -1e30f;
            float bv = -1e30f; int bl = 0;
            #pragma unroll
            for (int i = 0; i < LL; i++) {
                float f = __shfl_sync(FULLM, fin, i);
                if (f > bv) { bv = f; bl = i; }         // first-max wins
            }
            if (lane == 0) best_last_sh = bl;
        }
        __syncthreads();

        // ---- 72 parallel chases; argmax RECOMPUTED from stored scores (bit-identical) ----
        if (tid < 72) {
            int c = tid / 9, e = tid - c*9;
            int thi = (c == 7) ? (SS-1) : (c*64 + 64);
            int cur = e;
            for (int t = thi; t >= c*64 + 1; t--) {
                const float* sp = s_sh + (size_t)(t-1)*SROW;
                float v[LL];
                #pragma unroll
                for (int i = 0; i < LL; i++) v[i] = sp[i] + tr_sh[i*LL + cur];
                float best = max9(v);
                int bi = 8;
                #pragma unroll
                for (int i = 7; i >= 0; i--) bi = (v[i] == best) ? i : bi;   // first-max wins
                cur = m_sh[t] ? bi : cur;
                seg[c*9 + e][t - 1 - c*64] = (unsigned char)cur;
            }
        }
        __syncthreads();
        if (tid == 0) {
            int cur = best_last_sh;
            chosen[7] = (unsigned char)cur;
            for (int c = 7; c >= 1; c--) {
                cur = seg[c*9 + cur][0];
                chosen[c-1] = (unsigned char)cur;
            }
        }
        __syncthreads();

        // ---- one-hot ----
        float* outp = out + 1 + (size_t)b * SS * LL;
        int bl = best_last_sh;
        for (int idx = tid; idx < SS*LL; idx += 256) {
            int t = idx / LL;
            int l = idx - t*LL;
            int c = t >> 6;
            int tag = (t == SS-1) ? bl : (int)seg[c*9 + chosen[c]][t & 63];
            outp[idx] = (m_sh[t] && tag == l) ? 1.f : 0.f;
        }
    } else {
        // ---------------- lognorm blocks (R12 proven, unchanged) ----------------
        float* em_s = (float*)(shraw + SH_S);
        {
            const float4* src = reinterpret_cast<const float4*>(g_logits + (size_t)b * SS * LL);
            float4* dst = reinterpret_cast<float4*>(em_s);
            for (int k = tid; k < SS*LL/4; k += 256) dst[k] = src[k];
            for (int k = tid; k < SS; k += 256) m_sh[k] = (unsigned char)(mp[k] != 0);
            if (tid < LL) em_s[SS*LL + tid] = 0.f;
            if (tid == 0) m_sh[SS] = 0;
        }
        __syncthreads();

        float* lnM_s = (float*)(shraw + SH_LNM);
        if (w < 6) {
            int c = w / 3, trio = w - c*3;
            int gg = lane / 9, jj = lane - gg*9;
            if (gg > 2) { gg = 0; jj = lane - 27; }
            int gbase = gg * 9;
            bool act = (lane < 27);
            int e = trio*3 + gg;

            float u[LL];
            #pragma unroll
            for (int k = 0; k < LL; k++) u[k] = ex2f(tr[k*LL + jj] * L2E);

            float wv = (act && jj == e) ? 1.f : 0.f;
            int Ce = 0;
            int t0 = c*256 + 1;
            for (int oo = 0; oo < 32; oo++) {
                #pragma unroll
                for (int k = 0; k < 8; k++) {
                    int t = t0 + oo*8 + k;
                    float pe = ex2f(em_s[t*LL + jj] * L2E);
                    int m = m_sh[t];
                    float wi[LL];
                    #pragma unroll
                    for (int q = 0; q < LL; q++) wi[q] = __shfl_sync(FULLM, wv, gbase + q) * u[q];
                    float p = ((wi[0]+wi[1]) + (wi[2]+wi[3])) + ((wi[4]+wi[5]) + (wi[6]+wi[7])) + wi[8];
                    float nw = p * pe;
                    wv = m ? nw : wv;
                }
                float mx = wv;
                #pragma unroll
                for (int q = 0; q < LL; q++) mx = fmaxf(mx, __shfl_sync(FULLM, wv, gbase + q));
                int e2 = ((__float_as_int(mx) >> 23) & 0xFF) - 127;
                Ce += e2;
                wv *= __int_as_float((127 - e2) << 23);
            }
            if (act) lnM_s[(c*LL + e)*LL + jj] = lg2f(wv) + (float)Ce;
            asm volatile("bar.sync 1, 224;" ::: "memory");
        } else if (w == 6) {
            const int* lp = labels + b * SS;
            float acc = 0.f; int cnt = 0;
            for (int t = lane; t < SS; t += 32) {
                int m = m_sh[t]; cnt += m;
                if (t >= 1 && m) {
                    int tg = lp[t];   if (tg == -100) tg = 0;
                    int tp = lp[t-1]; if (tp == -100) tp = 0;
                    acc += em_s[t*LL + tg] + tr[tp*LL + tg];
                }
            }
            #pragma unroll
            for (int o = 16; o > 0; o >>= 1) {
                acc += __shfl_down_sync(FULLM, acc, o);
                cnt += __shfl_down_sync(FULLM, cnt, o);
            }
            float num = 0.f;
            if (lane == 0) {
                int t0 = lp[0]; if (t0 == -100) t0 = 0;
                int lt = lp[cnt - 1]; if (lt == -100) lt = 0;
                num = st[t0] + em_s[t0] + acc + en[lt];
            }
            asm volatile("bar.sync 1, 224;" ::: "memory");

            int j2 = (lane < LL) ? lane : (LL-1);
            bool l9 = (lane < LL);
            float v = l9 ? (st[j2] + em_s[j2]) * L2E : -1e30f;
            #pragma unroll
            for (int c = 0; c < 2; c++) {
                float s[LL];
                #pragma unroll
                for (int i = 0; i < LL; i++) s[i] = __shfl_sync(FULLM, v, i) + lnM_s[(c*LL + i)*LL + j2];
                float mx = max9(s);
                float p = 0.f;
                #pragma unroll
                for (int i = 0; i < LL; i++) p += ex2f(s[i] - mx);
                v = mx + lg2f(p);
            }
            float F = l9 ? (v + en[j2] * L2E) : -1e30f;
            float fv[LL];
            #pragma unroll
            for (int i = 0; i < LL; i++) fv[i] = __shfl_sync(FULLM, F, i);
            float mx = max9(fv);
            float p = 0.f;
            #pragma unroll
            for (int i = 0; i < LL; i++) p += ex2f(fv[i] - mx);
            if (lane == 0) {
                g_nd[b] = num - (mx + lg2f(p)) * (1.0f / L2E);
                __threadfence();
            }
        }
    }

    // ================= last block: loss + counter reset =================
    __syncthreads();
    if (tid == 0) {
        __threadfence();
        unsigned o = atomicAdd(&g_ctr, 1u);
        last_sh = (o == 2*BB - 1);
    }
    __syncthreads();
    if (last_sh) {
        __threadfence();
        if (tid < 32) {
            float x = g_nd[tid] + g_nd[tid + 32];
            #pragma unroll
            for (int o = 16; o > 0; o >>= 1) x += __shfl_down_sync(FULLM, x, o);
            if (tid == 0) { out[0] = -x / (float)BB; g_ctr = 0; }
        }
    }
}

extern "C" void kernel_launch(void* const* d_in, const int* in_sizes, int n_in,
                              void* d_out, int out_size) {
    const float* hidden = (const float*)d_in[0];
    const int*   mask   = (const int*)  d_in[1];
    const int*   labels = (const int*)  d_in[2];
    const float* W      = (const float*)d_in[3];
    const float* bvec   = (const float*)d_in[4];
    const float* st     = (const float*)d_in[5];
    const float* en     = (const float*)d_in[6];
    const float* tr     = (const float*)d_in[7];
    float* out = (float*)d_out;

    gemm_kernel<<<BS/64, 256>>>(hidden, W, bvec);
    fused_kernel<<<2*BB, 256>>>(mask, labels, st, en, tr, out);
}